// round 1
// baseline (speedup 1.0000x reference)
#include <cuda_runtime.h>
#include <math.h>

// ---------------- static scratch (no allocations allowed) ----------------
#define MAXN 100000
#define MAXE 1600000

__device__ float g_h [(size_t)MAXN * 128];   // current layer features (<=128 wide)
__device__ float g_hp[(size_t)MAXN * 64];    // activated layer output (64 wide)
__device__ float g_asrc[MAXN * 8];
__device__ float g_adst[MAXN * 8];
__device__ int   g_deg[MAXN];
__device__ int   g_off[MAXN + 1];
__device__ int   g_cur[MAXN];
__device__ int   g_csr[MAXE];

__device__ __forceinline__ float lrelu(float x) { return x > 0.f ? x : 0.2f * x; }

// ---------------- CSR build ----------------
__global__ void k_zero_deg(int N) {
    int i = blockIdx.x * blockDim.x + threadIdx.x;
    if (i < N) g_deg[i] = 0;
}

__global__ void k_count(const int* __restrict__ ei, int E) {
    int e = blockIdx.x * blockDim.x + threadIdx.x;
    if (e < E) atomicAdd(&g_deg[ei[E + e]], 1);
}

// one block, 1024 threads: exclusive scan of degrees -> g_off, copy -> g_cur
__global__ void k_scan(int N, int E) {
    __shared__ int ssum[1024];
    int t = threadIdx.x;
    int chunk = (N + 1023) / 1024;
    int lo = t * chunk;
    int hi = min(lo + chunk, N);
    int s = 0;
    for (int i = lo; i < hi; i++) s += g_deg[i];
    ssum[t] = s;
    __syncthreads();
    for (int d = 1; d < 1024; d <<= 1) {
        int v = (t >= d) ? ssum[t - d] : 0;
        __syncthreads();
        ssum[t] += v;
        __syncthreads();
    }
    int run = ssum[t] - s;  // exclusive prefix
    for (int i = lo; i < hi; i++) {
        g_off[i] = run;
        g_cur[i] = run;
        run += g_deg[i];
    }
    if (t == 0) g_off[N] = E;
}

__global__ void k_scatter(const int* __restrict__ ei, int E) {
    int e = blockIdx.x * blockDim.x + threadIdx.x;
    if (e < E) {
        int src = ei[e];
        int dst = ei[E + e];
        int pos = atomicAdd(&g_cur[dst], 1);
        g_csr[pos] = src;
    }
}

// ---------------- SGEMM: C[M,N] = [A1|A2] @ W,  K1%16==0, K2%16==0 ----------------
// tile 128x64, 256 threads, 8x4 microtile
__global__ void k_sgemm(const float* __restrict__ A1, int K1,
                        const float* __restrict__ A2, int K2,
                        const float* __restrict__ W, int N,
                        float* __restrict__ Cmat, int M) {
    __shared__ float As[16][128];
    __shared__ float Ws[16][64];
    int row0 = blockIdx.x * 128;
    int col0 = blockIdx.y * 64;
    int tid = threadIdx.x;
    int tx = tid & 15;    // 4 cols each
    int ty = tid >> 4;    // 8 rows each
    float acc[8][4];
#pragma unroll
    for (int i = 0; i < 8; i++)
#pragma unroll
        for (int j = 0; j < 4; j++) acc[i][j] = 0.f;

    int K = K1 + K2;
    for (int k0 = 0; k0 < K; k0 += 16) {
        // A tile (transposed store): 128 rows x 16 k, 2 float4 per thread
#pragma unroll
        for (int p = 0; p < 2; p++) {
            int q = tid * 2 + p;      // 0..511
            int r = q >> 2;           // 0..127
            int kk = (q & 3) * 4;
            int grow = row0 + r;
            float4 v = make_float4(0.f, 0.f, 0.f, 0.f);
            int kg = k0 + kk;
            if (grow < M) {
                const float* src = (kg < K1) ? (A1 + (size_t)grow * K1 + kg)
                                             : (A2 + (size_t)grow * K2 + (kg - K1));
                v = *(const float4*)src;
            }
            As[kk + 0][r] = v.x;
            As[kk + 1][r] = v.y;
            As[kk + 2][r] = v.z;
            As[kk + 3][r] = v.w;
        }
        // W tile: 16 x 64, 1 float4 per thread
        {
            int kk = tid >> 4;
            int c4 = (tid & 15) * 4;
            *(float4*)&Ws[kk][c4] = *(const float4*)(W + (size_t)(k0 + kk) * N + col0 + c4);
        }
        __syncthreads();
#pragma unroll
        for (int k = 0; k < 16; k++) {
            float4 a0 = *(const float4*)&As[k][ty * 8];
            float4 a1 = *(const float4*)&As[k][ty * 8 + 4];
            float4 b = *(const float4*)&Ws[k][tx * 4];
            float a[8] = {a0.x, a0.y, a0.z, a0.w, a1.x, a1.y, a1.z, a1.w};
            float bb[4] = {b.x, b.y, b.z, b.w};
#pragma unroll
            for (int i = 0; i < 8; i++)
#pragma unroll
                for (int j = 0; j < 4; j++) acc[i][j] += a[i] * bb[j];
        }
        __syncthreads();
    }
#pragma unroll
    for (int i = 0; i < 8; i++) {
        int grow = row0 + ty * 8 + i;
        if (grow < M) {
            float4 v = make_float4(acc[i][0], acc[i][1], acc[i][2], acc[i][3]);
            *(float4*)(Cmat + (size_t)grow * N + col0 + tx * 4) = v;
        }
    }
}

// ---------------- attention scores: a_src/a_dst [N,8] ----------------
template <int C>
__global__ void k_att(const float* __restrict__ hf, const float* __restrict__ att_s,
                      const float* __restrict__ att_d, int N) {
    int idx = blockIdx.x * blockDim.x + threadIdx.x;
    if (idx >= N * 8) return;
    int hh = idx & 7;
    const float* hp = hf + (size_t)(idx >> 3) * 8 * C + hh * C;
    float s = 0.f, d = 0.f;
#pragma unroll
    for (int c = 0; c < C; c++) {
        float v = hp[c];
        s += v * att_s[hh * C + c];
        d += v * att_d[hh * C + c];
    }
    g_asrc[idx] = s;
    g_adst[idx] = d;
}

// ---------------- aggregation: warp per node, two-pass softmax ----------------
// MODE 0: concat(8*C) + bias + PReLU -> out[N, 8*C]
// MODE 1: mean over heads + bias + log_softmax -> out[N, C]   (C=16)
template <int C, int MODE>
__global__ void k_agg(const float* __restrict__ hf, const float* __restrict__ bias,
                      const float* __restrict__ prelu_p, float* __restrict__ out, int N) {
    constexpr int F = 8 * C;
    constexpr int FPL = F / 32;
    int wib = threadIdx.x >> 5;
    int lane = threadIdx.x & 31;
    int n = blockIdx.x * (blockDim.x >> 5) + wib;
    if (n >= N) return;

    __shared__ float sm[8][8];
    __shared__ float ss[8][8];

    int start = g_off[n];
    int deg = g_off[n + 1] - start;

    int hh = lane & 7;
    float adst_h = g_adst[n * 8 + hh];

    // pass 1: per-head max (self-loop included), lanes = (edge%4, head)
    float m = lrelu(g_asrc[n * 8 + hh] + adst_h);
    for (int j = (lane >> 3); j < deg; j += 4) {
        int s = g_csr[start + j];
        m = fmaxf(m, lrelu(g_asrc[s * 8 + hh] + adst_h));
    }
    m = fmaxf(m, __shfl_xor_sync(0xffffffffu, m, 8));
    m = fmaxf(m, __shfl_xor_sync(0xffffffffu, m, 16));
    if (lane < 8) sm[wib][lane] = m;
    __syncwarp();

    // pass 2: accumulate exp weights and weighted features
    float acc[FPL];
#pragma unroll
    for (int i = 0; i < FPL; i++) acc[i] = 0.f;
    float sreg = 0.f;

    for (int j = -1; j < deg; j++) {
        int s = (j < 0) ? n : g_csr[start + j];
        float e = lrelu(g_asrc[s * 8 + hh] + adst_h);
        float w = __expf(e - m);  // valid for head hh in every lane
        if (lane < 8) sreg += w;
#pragma unroll
        for (int i = 0; i < FPL; i++) {
            int f = lane + 32 * i;
            float wi = __shfl_sync(0xffffffffu, w, f / C);
            acc[i] += wi * hf[(size_t)s * F + f];
        }
    }
    if (lane < 8) ss[wib][lane] = sreg;
    __syncwarp();

    if (MODE == 0) {
        float pa = prelu_p[0];
#pragma unroll
        for (int i = 0; i < FPL; i++) {
            int f = lane + 32 * i;
            float sden = ss[wib][f / C] + 1e-16f;
            float v = acc[i] / sden + bias[f];
            out[(size_t)n * F + f] = (v >= 0.f) ? v : pa * v;
        }
    } else {
        // mean over 8 heads, +bias, log_softmax over C=16 columns
        float vsum = 0.f;
#pragma unroll
        for (int i = 0; i < FPL; i++) {
            int f = lane + 32 * i;
            vsum += acc[i] / (ss[wib][f / C] + 1e-16f);
        }
        vsum += __shfl_xor_sync(0xffffffffu, vsum, 16);
        int c = lane & 15;
        float val = vsum * 0.125f + bias[c];
        float mx = val;
#pragma unroll
        for (int o = 8; o >= 1; o >>= 1) mx = fmaxf(mx, __shfl_xor_sync(0xffffffffu, mx, o));
        float se = expf(val - mx);
#pragma unroll
        for (int o = 8; o >= 1; o >>= 1) se += __shfl_xor_sync(0xffffffffu, se, o);
        float res = val - mx - logf(se);
        if (lane < 16) out[(size_t)n * C + c] = res;
    }
}

// ---------------- launch ----------------
extern "C" void kernel_launch(void* const* d_in, const int* in_sizes, int n_in,
                              void* d_out, int out_size) {
    const float* x   = (const float*)d_in[0];
    const int*   ei  = (const int*)d_in[1];
    const float* W1  = (const float*)d_in[2];
    const float* as1 = (const float*)d_in[3];
    const float* ad1 = (const float*)d_in[4];
    const float* b1  = (const float*)d_in[5];
    const float* W2  = (const float*)d_in[6];
    const float* as2 = (const float*)d_in[7];
    const float* ad2 = (const float*)d_in[8];
    const float* b2  = (const float*)d_in[9];
    const float* W3  = (const float*)d_in[10];
    const float* as3 = (const float*)d_in[11];
    const float* ad3 = (const float*)d_in[12];
    const float* b3  = (const float*)d_in[13];
    const float* p1  = (const float*)d_in[14];
    const float* p2  = (const float*)d_in[15];
    float* out = (float*)d_out;

    int N = in_sizes[0] / 256;
    int E = in_sizes[1] / 2;

    float *hbuf, *hpbuf;
    cudaGetSymbolAddress((void**)&hbuf, g_h);
    cudaGetSymbolAddress((void**)&hpbuf, g_hp);

    int gb256N = (N + 255) / 256;
    int gb256E = (E + 255) / 256;
    int gbAtt = (N * 8 + 255) / 256;
    int gbAgg = (N + 7) / 8;           // 8 warps/block
    int gbM = (N + 127) / 128;

    // CSR by destination (shared by all 3 layers)
    k_zero_deg<<<gb256N, 256>>>(N);
    k_count<<<gb256E, 256>>>(ei, E);
    k_scan<<<1, 1024>>>(N, E);
    k_scatter<<<gb256E, 256>>>(ei, E);

    // Layer 1: h1 = x@W1 -> agg -> PReLU -> hp
    k_sgemm<<<dim3(gbM, 1), 256>>>(x, 256, nullptr, 0, W1, 64, hbuf, N);
    k_att<8><<<gbAtt, 256>>>(hbuf, as1, ad1, N);
    k_agg<8, 0><<<gbAgg, 256>>>(hbuf, b1, p1, hpbuf, N);

    // Layer 2: h2 = [x|hp]@W2 -> agg -> PReLU -> hp
    k_sgemm<<<dim3(gbM, 1), 256>>>(x, 256, hpbuf, 64, W2, 64, hbuf, N);
    k_att<8><<<gbAtt, 256>>>(hbuf, as2, ad2, N);
    k_agg<8, 0><<<gbAgg, 256>>>(hbuf, b2, p2, hpbuf, N);

    // Layer 3: h3 = hp@W3 -> agg(mean) -> log_softmax -> out
    k_sgemm<<<dim3(gbM, 2), 256>>>(hpbuf, 64, nullptr, 0, W3, 128, hbuf, N);
    k_att<16><<<gbAtt, 256>>>(hbuf, as3, ad3, N);
    k_agg<16, 1><<<gbAgg, 256>>>(hbuf, b3, nullptr, out, N);
}